// round 2
// baseline (speedup 1.0000x reference)
#include <cuda_runtime.h>
#include <cuda_bf16.h>
#include <cstdint>

// B=1024, S=200, D=64, C=256
// Inputs: rq_item_embeddings f32 [B,S,D], labels i32 [B,S], attention_mask i32 [B,S]
// Output (float32, concatenated):
//   [0 .. B*C*D)             cluster_emb
//   [B*C*D .. +B*C*S)        cluster_mask (0.0f/1.0f)

namespace {
constexpr int B = 1024;
constexpr int S = 200;
constexpr int D = 64;
constexpr int C = 256;

constexpr int SMEM_LAB_BYTES = 1024;        // 200 ints padded
constexpr int SMEM_ACC_BYTES = C * D * 4;   // 65536
constexpr int SMEM_CNT_BYTES = C * 4;       // 1024
constexpr int SMEM_EMB_TOTAL = SMEM_LAB_BYTES + SMEM_ACC_BYTES + SMEM_CNT_BYTES;

constexpr int MASK_SPLIT = 4;               // C-range chunks per batch
constexpr int C_CHUNK = C / MASK_SPLIT;     // 64 clusters per block
}

// ---------------------------------------------------------------------------
// Kernel 1: cluster_emb accumulation (smem-heavy, 3 CTAs/SM)
// ---------------------------------------------------------------------------
__global__ __launch_bounds__(256) void s3rec_emb_kernel(
    const float* __restrict__ x,
    const int*   __restrict__ labels,
    const int*   __restrict__ amask,
    float*       __restrict__ out)
{
    extern __shared__ char smem[];
    int*   lab    = reinterpret_cast<int*>(smem);
    float* acc    = reinterpret_cast<float*>(smem + SMEM_LAB_BYTES);
    int*   counts = reinterpret_cast<int*>(smem + SMEM_LAB_BYTES + SMEM_ACC_BYTES);

    const int b   = blockIdx.x;
    const int tid = threadIdx.x;

    for (int s = tid; s < S; s += 256) {
        int m = amask[b * S + s];
        lab[s] = m ? labels[b * S + s] : -1;
    }
    #pragma unroll 4
    for (int i = tid; i < (C * D) / 4; i += 256)
        reinterpret_cast<float4*>(acc)[i] = make_float4(0.f, 0.f, 0.f, 0.f);
    if (tid < C) counts[tid] = 0;
    __syncthreads();

    {
        const int w    = tid >> 5;
        const int lane = tid & 31;
        for (int s = w; s < S; s += 8) {
            int c = lab[s];
            if (c >= 0) {
                if (lane == 0) atomicAdd(&counts[c], 1);
                const float2 v = reinterpret_cast<const float2*>(
                    x + ((size_t)b * S + s) * D)[lane];
                atomicAdd(&acc[c * D + lane * 2],     v.x);
                atomicAdd(&acc[c * D + lane * 2 + 1], v.y);
            }
        }
    }
    __syncthreads();

    float* embOut = out + (size_t)b * C * D;
    #pragma unroll 4
    for (int i = tid; i < (C * D) / 4; i += 256) {
        float4 v = reinterpret_cast<float4*>(acc)[i];
        int   c   = i >> 4;          // (i*4)/64
        int   cnt = counts[c];
        float inv = (cnt > 0) ? (1.0f / (float)cnt) : 0.0f;
        v.x *= inv; v.y *= inv; v.z *= inv; v.w *= inv;
        reinterpret_cast<float4*>(embOut)[i] = v;
    }
}

// ---------------------------------------------------------------------------
// Kernel 2: cluster_mask streaming writer (smem-light, high occupancy)
// grid = B * MASK_SPLIT; block handles C_CHUNK clusters of one batch.
// ---------------------------------------------------------------------------
__global__ __launch_bounds__(256) void s3rec_mask_kernel(
    const int* __restrict__ labels,
    const int* __restrict__ amask,
    float*     __restrict__ out)
{
    __shared__ int lab[256];   // 200 used

    const int b     = blockIdx.x >> 2;          // / MASK_SPLIT
    const int chunk = blockIdx.x & 3;           // % MASK_SPLIT
    const int tid   = threadIdx.x;

    for (int s = tid; s < S; s += 256) {
        int m = amask[b * S + s];
        lab[s] = m ? labels[b * S + s] : -1;
    }
    __syncthreads();

    const int cBase = chunk * C_CHUNK;
    float* maskOut = out + (size_t)B * C * D
                         + (size_t)b * C * S
                         + (size_t)cBase * S;

    // C_CHUNK*S/4 = 3200 float4 per block -> 12.5 per thread
    constexpr int NQ = C_CHUNK * S / 4;
    #pragma unroll 4
    for (int i = tid; i < NQ; i += 256) {
        const int c  = cBase + i / (S / 4);
        const int s0 = (i % (S / 4)) * 4;
        float4 v;
        v.x = (lab[s0 + 0] == c) ? 1.0f : 0.0f;
        v.y = (lab[s0 + 1] == c) ? 1.0f : 0.0f;
        v.z = (lab[s0 + 2] == c) ? 1.0f : 0.0f;
        v.w = (lab[s0 + 3] == c) ? 1.0f : 0.0f;
        reinterpret_cast<float4*>(maskOut)[i] = v;
    }
}

extern "C" void kernel_launch(void* const* d_in, const int* in_sizes, int n_in,
                              void* d_out, int out_size)
{
    const float* x      = (const float*)d_in[0];
    const int*   labels = (const int*)d_in[1];
    const int*   amask  = (const int*)d_in[2];
    float*       out    = (float*)d_out;

    cudaFuncSetAttribute(s3rec_emb_kernel,
                         cudaFuncAttributeMaxDynamicSharedMemorySize, SMEM_EMB_TOTAL);

    s3rec_mask_kernel<<<B * MASK_SPLIT, 256>>>(labels, amask, out);
    s3rec_emb_kernel<<<B, 256, SMEM_EMB_TOTAL>>>(x, labels, amask, out);
}

// round 3
// speedup vs baseline: 1.3369x; 1.3369x over previous
#include <cuda_runtime.h>
#include <cuda_bf16.h>
#include <cstdint>

// B=1024, S=200, D=64, C=256
// Inputs: rq_item_embeddings f32 [B,S,D], labels i32 [B,S], attention_mask i32 [B,S]
// Output (float32, concatenated):
//   [0 .. B*C*D)             cluster_emb
//   [B*C*D .. +B*C*S)        cluster_mask (0.0f/1.0f)

namespace {
constexpr int B = 1024;
constexpr int S = 200;
constexpr int D = 64;
constexpr int C = 256;
}

__global__ __launch_bounds__(256) void s3rec_fused_kernel(
    const float* __restrict__ x,       // [B,S,D]
    const int*   __restrict__ labels,  // [B,S]
    const int*   __restrict__ amask,   // [B,S]
    float*       __restrict__ out)
{
    __shared__ int lab[208];        // fused label+mask (-1 = masked out)
    __shared__ int cnt[256];        // per-cluster member count
    __shared__ int scan[256];       // inclusive scan workspace
    __shared__ int startA[256];     // exclusive prefix (cluster -> slot base)
    __shared__ int cursor[256];     // scatter cursors
    __shared__ int order[208];      // s-indices sorted by cluster

    const int b    = blockIdx.x;
    const int tid  = threadIdx.x;
    const int w    = tid >> 5;
    const int lane = tid & 31;

    // ---- Phase 1: labels + counts -------------------------------------
    cnt[tid] = 0;
    __syncthreads();
    if (tid < S) {
        int m = amask[b * S + tid];
        int l = m ? labels[b * S + tid] : -1;
        lab[tid] = l;
        if (l >= 0) atomicAdd(&cnt[l], 1);
    }
    __syncthreads();

    // ---- Phase 2: exclusive scan (Hillis-Steele, 256 lanes) -----------
    int v = cnt[tid];
    scan[tid] = v;
    __syncthreads();
    #pragma unroll
    for (int off = 1; off < 256; off <<= 1) {
        int t = (tid >= off) ? scan[tid - off] : 0;
        __syncthreads();
        scan[tid] += t;
        __syncthreads();
    }
    int st = scan[tid] - v;
    startA[tid] = st;
    cursor[tid] = st;
    __syncthreads();

    // ---- Phase 3: scatter s-indices into cluster-sorted order ---------
    if (tid < S) {
        int c = lab[tid];
        if (c >= 0) {
            int p = atomicAdd(&cursor[c], 1);
            order[p] = tid;
        }
    }
    __syncthreads();

    // ---- Phase 4: gather per cluster, accumulate in registers ---------
    // warp w handles clusters w, w+8, ... (32 clusters/warp)
    {
        const float* xb = x + (size_t)b * S * D;
        float* embOut = out + (size_t)b * C * D;
        for (int c = w; c < C; c += 8) {
            const int k  = cnt[c];
            const int s0 = startA[c];
            float ax = 0.f, ay = 0.f;
            for (int j = 0; j < k; j++) {
                const int s = order[s0 + j];
                const float2 vv = reinterpret_cast<const float2*>(xb + s * D)[lane];
                ax += vv.x; ay += vv.y;
            }
            const float inv = (k > 0) ? (1.0f / (float)k) : 0.0f;
            float2 o; o.x = ax * inv; o.y = ay * inv;
            reinterpret_cast<float2*>(embOut + c * D)[lane] = o;
        }
    }

    // ---- Phase 5: mask stream-out (float4 one-hot compares) -----------
    {
        float* maskOut = out + (size_t)B * C * D + (size_t)b * C * S;
        constexpr int NQ = C * S / 4;   // 12800
        #pragma unroll 4
        for (int i = tid; i < NQ; i += 256) {
            const int c  = i / (S / 4);
            const int s0 = (i % (S / 4)) * 4;
            float4 m;
            m.x = (lab[s0 + 0] == c) ? 1.0f : 0.0f;
            m.y = (lab[s0 + 1] == c) ? 1.0f : 0.0f;
            m.z = (lab[s0 + 2] == c) ? 1.0f : 0.0f;
            m.w = (lab[s0 + 3] == c) ? 1.0f : 0.0f;
            reinterpret_cast<float4*>(maskOut)[i] = m;
        }
    }
}

extern "C" void kernel_launch(void* const* d_in, const int* in_sizes, int n_in,
                              void* d_out, int out_size)
{
    const float* x      = (const float*)d_in[0];
    const int*   labels = (const int*)d_in[1];
    const int*   amask  = (const int*)d_in[2];
    float*       out    = (float*)d_out;

    s3rec_fused_kernel<<<B, 256>>>(x, labels, amask, out);
}

// round 4
// speedup vs baseline: 1.4002x; 1.0474x over previous
#include <cuda_runtime.h>
#include <cuda_bf16.h>
#include <cstdint>

// B=1024, S=200, D=64, C=256
// Inputs: rq_item_embeddings f32 [B,S,D], labels i32 [B,S], attention_mask i32 [B,S]
// Output (float32, concatenated):
//   [0 .. B*C*D)             cluster_emb
//   [B*C*D .. +B*C*S)        cluster_mask (0.0f/1.0f)

namespace {
constexpr int B = 1024;
constexpr int S = 200;
constexpr int D = 64;
constexpr int C = 256;
}

__global__ __launch_bounds__(256) void s3rec_fused_kernel(
    const float* __restrict__ x,       // [B,S,D]
    const int*   __restrict__ labels,  // [B,S]
    const int*   __restrict__ amask,   // [B,S]
    float*       __restrict__ out)
{
    __shared__ int lab[208];        // fused label+mask (-1 = masked out)
    __shared__ int cnt[256];        // per-cluster member count
    __shared__ int startA[256];     // exclusive prefix (cluster -> slot base)
    __shared__ int cursor[256];     // scatter cursors
    __shared__ int order[208];      // s-indices sorted by cluster
    __shared__ int waggr[8];        // per-warp scan aggregates

    const int b    = blockIdx.x;
    const int tid  = threadIdx.x;
    const int w    = tid >> 5;
    const int lane = tid & 31;

    float* maskOut = out + (size_t)B * C * D + (size_t)b * C * S;

    // ---- Phase 0: issue label loads, then zero-fill mask (no deps) ----
    int myLab = -1;
    if (tid < S) {
        int m = amask[b * S + tid];
        myLab = m ? labels[b * S + tid] : -1;
        lab[tid] = myLab;
    }
    cnt[tid] = 0;

    {
        const float4 z4 = make_float4(0.f, 0.f, 0.f, 0.f);
        float4* mq = reinterpret_cast<float4*>(maskOut);
        constexpr int NQ = C * S / 4;   // 12800 quads, 50/thread
        #pragma unroll 5
        for (int i = tid; i < NQ; i += 256)
            __stcs(mq + i, z4);
    }
    __syncthreads();

    // ---- Phase 1: counts + scatter the 1.0f mask entries --------------
    if (myLab >= 0) {
        atomicAdd(&cnt[myLab], 1);
        maskOut[myLab * S + tid] = 1.0f;   // after zero-fill barrier
    }
    __syncthreads();

    // ---- Phase 2: exclusive scan via shfl (3 barriers total) ----------
    const int v = cnt[tid];
    int incl = v;
    #pragma unroll
    for (int off = 1; off < 32; off <<= 1) {
        int t = __shfl_up_sync(0xFFFFFFFFu, incl, off);
        if (lane >= off) incl += t;
    }
    if (lane == 31) waggr[w] = incl;
    __syncthreads();
    if (tid < 8) {
        int a = waggr[tid];
        int s = a;
        #pragma unroll
        for (int off = 1; off < 8; off <<= 1) {
            int t = __shfl_up_sync(0xFFu, s, off);
            if (tid >= off) s += t;
        }
        waggr[tid] = s - a;   // exclusive warp offset
    }
    __syncthreads();
    const int st = incl - v + waggr[w];
    startA[tid] = st;
    cursor[tid] = st;
    __syncthreads();

    // ---- Phase 3: scatter s-indices into cluster-sorted order ---------
    if (myLab >= 0) {
        int p = atomicAdd(&cursor[myLab], 1);
        order[p] = tid;
    }
    __syncthreads();

    // ---- Phase 4: gather per cluster, accumulate in registers ---------
    {
        const float* xb = x + (size_t)b * S * D;
        float* embOut = out + (size_t)b * C * D;
        for (int c = w; c < C; c += 8) {
            const int k  = cnt[c];
            const int s0 = startA[c];
            float ax = 0.f, ay = 0.f;
            for (int j = 0; j < k; j++) {
                const int s = order[s0 + j];
                const float2 vv = reinterpret_cast<const float2*>(xb + s * D)[lane];
                ax += vv.x; ay += vv.y;
            }
            const float inv = (k > 0) ? (1.0f / (float)k) : 0.0f;
            float2 o; o.x = ax * inv; o.y = ay * inv;
            __stcs(reinterpret_cast<float2*>(embOut + c * D) + lane, o);
        }
    }
}

extern "C" void kernel_launch(void* const* d_in, const int* in_sizes, int n_in,
                              void* d_out, int out_size)
{
    const float* x      = (const float*)d_in[0];
    const int*   labels = (const int*)d_in[1];
    const int*   amask  = (const int*)d_in[2];
    float*       out    = (float*)d_out;

    s3rec_fused_kernel<<<B, 256>>>(x, labels, amask, out);
}

// round 5
// speedup vs baseline: 1.6196x; 1.1567x over previous
#include <cuda_runtime.h>
#include <cuda_bf16.h>
#include <cstdint>

// B=1024, S=200, D=64, C=256
// Inputs: rq_item_embeddings f32 [B,S,D], labels i32 [B,S], attention_mask i32 [B,S]
// Output (float32, concatenated):
//   [0 .. B*C*D)             cluster_emb
//   [B*C*D .. +B*C*S)        cluster_mask (0.0f/1.0f)
//
// Grid = B*2: each CTA owns one batch b and one half of the cluster range
// (128 clusters). x rows are read exactly once (by the cluster-owning CTA).

namespace {
constexpr int B = 1024;
constexpr int S = 200;
constexpr int D = 64;
constexpr int C = 256;
constexpr int HALF = C / 2;           // 128 clusters per CTA
}

__global__ __launch_bounds__(256) void s3rec_fused_kernel(
    const float* __restrict__ x,       // [B,S,D]
    const int*   __restrict__ labels,  // [B,S]
    const int*   __restrict__ amask,   // [B,S]
    float*       __restrict__ out)
{
    __shared__ int lab[208];        // fused label+mask (-1 = masked out)
    __shared__ int cnt[HALF];       // per-local-cluster member count
    __shared__ int startA[HALF];    // exclusive prefix
    __shared__ int cursor[HALF];    // scatter cursors
    __shared__ int order[208];      // s-indices sorted by local cluster
    __shared__ int waggr[4];        // scan warp aggregates

    const int b    = blockIdx.x >> 1;
    const int h    = blockIdx.x & 1;      // cluster half
    const int tid  = threadIdx.x;
    const int w    = tid >> 5;
    const int lane = tid & 31;
    const int cBase = h * HALF;

    float* maskOutH = out + (size_t)B * C * D
                          + (size_t)b * C * S
                          + (size_t)cBase * S;

    // ---- Phase 0: label loads + zero-fill my half of the mask ---------
    int myLab = -1;
    if (tid < S) {
        int m = amask[b * S + tid];
        myLab = m ? labels[b * S + tid] : -1;
        lab[tid] = myLab;
    }
    if (tid < HALF) cnt[tid] = 0;

    {
        const float4 z4 = make_float4(0.f, 0.f, 0.f, 0.f);
        float4* mq = reinterpret_cast<float4*>(maskOutH);
        constexpr int NQ = HALF * S / 4;   // 6400 quads, 25/thread
        #pragma unroll 5
        for (int i = tid; i < NQ; i += 256)
            __stcs(mq + i, z4);
    }
    __syncthreads();

    // ---- Phase 1: counts + scatter 1.0f for my cluster half -----------
    const int cl = myLab - cBase;          // local cluster id (may be OOR)
    const bool mine = (cl >= 0) && (cl < HALF);
    if (mine) {
        atomicAdd(&cnt[cl], 1);
        maskOutH[cl * S + tid] = 1.0f;     // ordered after zero-fill barrier
    }
    __syncthreads();

    // ---- Phase 2: exclusive scan over 128 counts (4 warps, shfl) ------
    int v = 0, incl = 0;
    if (tid < HALF) {
        v = cnt[tid];
        incl = v;
        #pragma unroll
        for (int off = 1; off < 32; off <<= 1) {
            int t = __shfl_up_sync(0xFFFFFFFFu, incl, off);
            if (lane >= off) incl += t;
        }
        if (lane == 31) waggr[w] = incl;
    }
    __syncthreads();
    if (tid < 4) {
        int a = waggr[tid];
        int s = a;
        #pragma unroll
        for (int off = 1; off < 4; off <<= 1) {
            int t = __shfl_up_sync(0xFu, s, off);
            if (tid >= off) s += t;
        }
        waggr[tid] = s - a;                // exclusive warp offset
    }
    __syncthreads();
    if (tid < HALF) {
        int st = incl - v + waggr[w];
        startA[tid] = st;
        cursor[tid] = st;
    }
    __syncthreads();

    // ---- Phase 3: scatter s-indices into cluster-sorted order ---------
    if (mine) {
        int p = atomicAdd(&cursor[cl], 1);
        order[p] = tid;
    }
    __syncthreads();

    // ---- Phase 4: gather; half-warp per cluster, float4 lanes ---------
    // Each warp handles 2 clusters per pass (lanes 0-15 / 16-31),
    // 16 lanes x float4 = 64 floats = one D row.
    {
        const float* xb    = x + (size_t)b * S * D;
        float* embOut      = out + (size_t)b * C * D;
        const int hw  = lane >> 4;         // half-warp id (0/1)
        const int l16 = lane & 15;

        #pragma unroll
        for (int pass = 0; pass < HALF / 16; pass++) {   // 8 passes
            const int cLocal = pass * 16 + w * 2 + hw;
            const int k  = cnt[cLocal];
            const int s0 = startA[cLocal];
            float4 acc = make_float4(0.f, 0.f, 0.f, 0.f);
            for (int j = 0; j < k; j++) {
                const int s = order[s0 + j];
                const float4 vv = reinterpret_cast<const float4*>(xb + s * D)[l16];
                acc.x += vv.x; acc.y += vv.y; acc.z += vv.z; acc.w += vv.w;
            }
            const float inv = (k > 0) ? (1.0f / (float)k) : 0.0f;
            acc.x *= inv; acc.y *= inv; acc.z *= inv; acc.w *= inv;
            __stcs(reinterpret_cast<float4*>(embOut + (cBase + cLocal) * D) + l16, acc);
        }
    }
}

extern "C" void kernel_launch(void* const* d_in, const int* in_sizes, int n_in,
                              void* d_out, int out_size)
{
    const float* x      = (const float*)d_in[0];
    const int*   labels = (const int*)d_in[1];
    const int*   amask  = (const int*)d_in[2];
    float*       out    = (float*)d_out;

    s3rec_fused_kernel<<<B * 2, 256>>>(x, labels, amask, out);
}

// round 6
// speedup vs baseline: 1.6791x; 1.0368x over previous
#include <cuda_runtime.h>
#include <cuda_bf16.h>
#include <cstdint>

// B=1024, S=200, D=64, C=256
// Inputs: rq_item_embeddings f32 [B,S,D], labels i32 [B,S], attention_mask i32 [B,S]
// Output (float32, concatenated):
//   [0 .. B*C*D)             cluster_emb
//   [B*C*D .. +B*C*S)        cluster_mask (0.0f/1.0f)
//
// Grid = B*4: each CTA owns one batch b and one quarter of the cluster range
// (64 clusters). x rows are read exactly once (by the cluster-owning CTA).

namespace {
constexpr int B = 1024;
constexpr int S = 200;
constexpr int D = 64;
constexpr int C = 256;
constexpr int SPLIT = 4;
constexpr int CPART = C / SPLIT;      // 64 clusters per CTA
}

__global__ __launch_bounds__(256) void s3rec_fused_kernel(
    const float* __restrict__ x,       // [B,S,D]
    const int*   __restrict__ labels,  // [B,S]
    const int*   __restrict__ amask,   // [B,S]
    float*       __restrict__ out)
{
    __shared__ int lab[208];        // fused label+mask (-1 = masked out)
    __shared__ int cnt[CPART];      // per-local-cluster member count
    __shared__ int startA[CPART];   // exclusive prefix
    __shared__ int cursor[CPART];   // scatter cursors
    __shared__ int order[208];      // s-indices sorted by local cluster
    __shared__ int waggr[2];        // scan warp aggregates

    const int b    = blockIdx.x >> 2;
    const int part = blockIdx.x & 3;      // cluster quarter
    const int tid  = threadIdx.x;
    const int w    = tid >> 5;
    const int lane = tid & 31;
    const int cBase = part * CPART;

    float* maskOutP = out + (size_t)B * C * D
                          + (size_t)b * C * S
                          + (size_t)cBase * S;

    // ---- Phase 0: label loads + zero-fill my quarter of the mask ------
    int myLab = -1;
    if (tid < S) {
        int m = amask[b * S + tid];
        myLab = m ? labels[b * S + tid] : -1;
        lab[tid] = myLab;
    }
    if (tid < CPART) cnt[tid] = 0;

    {
        const float4 z4 = make_float4(0.f, 0.f, 0.f, 0.f);
        float4* mq = reinterpret_cast<float4*>(maskOutP);
        constexpr int NQ = CPART * S / 4;   // 3200 quads, 12.5/thread
        #pragma unroll 5
        for (int i = tid; i < NQ; i += 256)
            __stcs(mq + i, z4);
    }
    __syncthreads();

    // ---- Phase 1: counts + scatter 1.0f for my cluster quarter --------
    const int cl = myLab - cBase;          // local cluster id (may be OOR)
    const bool mine = (cl >= 0) && (cl < CPART);
    if (mine) {
        atomicAdd(&cnt[cl], 1);
        maskOutP[cl * S + tid] = 1.0f;     // ordered after zero-fill barrier
    }
    __syncthreads();

    // ---- Phase 2: exclusive scan over 64 counts (2 warps, shfl) -------
    int v = 0, incl = 0;
    if (tid < CPART) {
        v = cnt[tid];
        incl = v;
        #pragma unroll
        for (int off = 1; off < 32; off <<= 1) {
            int t = __shfl_up_sync(0xFFFFFFFFu, incl, off);
            if (lane >= off) incl += t;
        }
        if (lane == 31) waggr[w] = incl;
    }
    __syncthreads();
    if (tid == 0) waggr[1] += 0;           // no-op placeholder (single dep)
    if (tid < 2) {
        // exclusive offsets across the 2 warps
        int a0 = waggr[0];
        waggr[0] = 0;
        if (tid == 1) waggr[1] = a0;
    }
    __syncthreads();
    if (tid < CPART) {
        int st = incl - v + waggr[w];
        startA[tid] = st;
        cursor[tid] = st;
    }
    __syncthreads();

    // ---- Phase 3: scatter s-indices into cluster-sorted order ---------
    if (mine) {
        int p = atomicAdd(&cursor[cl], 1);
        order[p] = tid;
    }
    __syncthreads();

    // ---- Phase 4: gather; half-warp per cluster, float4 lanes ---------
    // Each warp handles 2 clusters per pass (lanes 0-15 / 16-31),
    // 16 lanes x float4 = 64 floats = one D row.  4 passes x 16 = 64.
    {
        const float* xb = x + (size_t)b * S * D;
        float* embOut   = out + (size_t)b * C * D;
        const int hw  = lane >> 4;         // half-warp id (0/1)
        const int l16 = lane & 15;

        #pragma unroll
        for (int pass = 0; pass < CPART / 16; pass++) {   // 4 passes
            const int cLocal = pass * 16 + w * 2 + hw;
            const int k  = cnt[cLocal];
            const int s0 = startA[cLocal];
            float4 acc = make_float4(0.f, 0.f, 0.f, 0.f);
            for (int j = 0; j < k; j++) {
                const int s = order[s0 + j];
                const float4 vv = reinterpret_cast<const float4*>(xb + s * D)[l16];
                acc.x += vv.x; acc.y += vv.y; acc.z += vv.z; acc.w += vv.w;
            }
            const float inv = (k > 0) ? (1.0f / (float)k) : 0.0f;
            acc.x *= inv; acc.y *= inv; acc.z *= inv; acc.w *= inv;
            __stcs(reinterpret_cast<float4*>(embOut + (cBase + cLocal) * D) + l16, acc);
        }
    }
}

extern "C" void kernel_launch(void* const* d_in, const int* in_sizes, int n_in,
                              void* d_out, int out_size)
{
    const float* x      = (const float*)d_in[0];
    const int*   labels = (const int*)d_in[1];
    const int*   amask  = (const int*)d_in[2];
    float*       out    = (float*)d_out;

    s3rec_fused_kernel<<<B * SPLIT, 256>>>(x, labels, amask, out);
}

// round 7
// speedup vs baseline: 1.6996x; 1.0122x over previous
#include <cuda_runtime.h>
#include <cuda_bf16.h>
#include <cstdint>

// B=1024, S=200, D=64, C=256
// Inputs: rq_item_embeddings f32 [B,S,D], labels i32 [B,S], attention_mask i32 [B,S]
// Output (float32, concatenated):
//   [0 .. B*C*D)             cluster_emb
//   [B*C*D .. +B*C*S)        cluster_mask (0.0f/1.0f)
//
// Grid = B*8: each CTA owns one batch b and a 32-cluster range.
// x rows are read exactly once (by the cluster-owning CTA); labels are
// re-read by sibling CTAs but stay L2-resident (1.6 MB total).

namespace {
constexpr int B = 1024;
constexpr int S = 200;
constexpr int D = 64;
constexpr int C = 256;
constexpr int SPLIT = 8;
constexpr int CPART = C / SPLIT;      // 32 clusters per CTA
}

__global__ __launch_bounds__(256) void s3rec_fused_kernel(
    const float* __restrict__ x,       // [B,S,D]
    const int*   __restrict__ labels,  // [B,S]
    const int*   __restrict__ amask,   // [B,S]
    float*       __restrict__ out)
{
    __shared__ int lab[208];        // fused label+mask (-1 = masked out)
    __shared__ int cnt[CPART];      // per-local-cluster member count
    __shared__ int startA[CPART];   // exclusive prefix
    __shared__ int cursor[CPART];   // scatter cursors
    __shared__ int order[208];      // s-indices sorted by local cluster

    const int b    = blockIdx.x >> 3;
    const int part = blockIdx.x & 7;      // cluster octant
    const int tid  = threadIdx.x;
    const int w    = tid >> 5;
    const int lane = tid & 31;
    const int cBase = part * CPART;

    float* maskOutP = out + (size_t)B * C * D
                          + (size_t)b * C * S
                          + (size_t)cBase * S;

    // ---- Phase 0: label loads + zero-fill my 32-cluster mask slab -----
    int myLab = -1;
    if (tid < S) {
        int m = __ldg(amask + b * S + tid);
        myLab = m ? __ldg(labels + b * S + tid) : -1;
        lab[tid] = myLab;
    }
    if (tid < CPART) cnt[tid] = 0;

    {
        const float4 z4 = make_float4(0.f, 0.f, 0.f, 0.f);
        float4* mq = reinterpret_cast<float4*>(maskOutP);
        constexpr int NQ = CPART * S / 4;   // 1600 quads, 6.25/thread
        #pragma unroll 7
        for (int i = tid; i < NQ; i += 256)
            __stcs(mq + i, z4);
    }
    __syncthreads();

    // ---- Phase 1: counts + scatter 1.0f for my cluster range ----------
    const int cl = myLab - cBase;          // local cluster id (may be OOR)
    const bool mine = (cl >= 0) && (cl < CPART);
    if (mine) {
        atomicAdd(&cnt[cl], 1);
        maskOutP[cl * S + tid] = 1.0f;     // ordered after zero-fill barrier
    }
    __syncthreads();

    // ---- Phase 2: exclusive scan over 32 counts (warp 0 only) ---------
    if (tid < 32) {
        const int v = cnt[tid];
        int incl = v;
        #pragma unroll
        for (int off = 1; off < 32; off <<= 1) {
            int t = __shfl_up_sync(0xFFFFFFFFu, incl, off);
            if (lane >= off) incl += t;
        }
        const int st = incl - v;
        startA[tid] = st;
        cursor[tid] = st;
    }
    __syncthreads();

    // ---- Phase 3: scatter s-indices into cluster-sorted order ---------
    if (mine) {
        int p = atomicAdd(&cursor[cl], 1);
        order[p] = tid;
    }
    __syncthreads();

    // ---- Phase 4: gather; half-warp per cluster, float4 lanes ---------
    // Each warp handles 2 clusters per pass (lanes 0-15 / 16-31),
    // 16 lanes x float4 = one D row. 2 passes x 16 = 32 clusters.
    {
        const float* xb = x + (size_t)b * S * D;
        float* embOut   = out + (size_t)b * C * D;
        const int hw  = lane >> 4;         // half-warp id (0/1)
        const int l16 = lane & 15;

        #pragma unroll
        for (int pass = 0; pass < CPART / 16; pass++) {   // 2 passes
            const int cLocal = pass * 16 + w * 2 + hw;
            const int k  = cnt[cLocal];
            const int s0 = startA[cLocal];
            float4 acc = make_float4(0.f, 0.f, 0.f, 0.f);
            if (k > 0) {
                // 2-deep pipeline: prefetch next order index
                int sCur = order[s0];
                for (int j = 0; j < k; j++) {
                    const int sNext = (j + 1 < k) ? order[s0 + j + 1] : 0;
                    const float4 vv =
                        reinterpret_cast<const float4*>(xb + sCur * D)[l16];
                    acc.x += vv.x; acc.y += vv.y; acc.z += vv.z; acc.w += vv.w;
                    sCur = sNext;
                }
                const float inv = 1.0f / (float)k;
                acc.x *= inv; acc.y *= inv; acc.z *= inv; acc.w *= inv;
            }
            __stcs(reinterpret_cast<float4*>(embOut + (cBase + cLocal) * D) + l16, acc);
        }
    }
}

extern "C" void kernel_launch(void* const* d_in, const int* in_sizes, int n_in,
                              void* d_out, int out_size)
{
    const float* x      = (const float*)d_in[0];
    const int*   labels = (const int*)d_in[1];
    const int*   amask  = (const int*)d_in[2];
    float*       out    = (float*)d_out;

    s3rec_fused_kernel<<<B * SPLIT, 256>>>(x, labels, amask, out);
}